// round 9
// baseline (speedup 1.0000x reference)
#include <cuda_runtime.h>
#include <cstdint>

#define NL   28
#define DIM  1024
#define NH   16
#define HD   64
#define FFN  2816
#define VOCAB 32000
#define GRIDSZ 296

// ---------------- device scratch ----------------
__device__ float g_h[2][DIM];              // residual stream (atomically updated)
__device__ float g_qkv[2][2][3 * DIM];     // [parity][batch][q|k|v]
__device__ float g_gp[2][2][2][FFN];       // [parity][gate/up][batch][col]
__device__ float g_hn[2][DIM];             // final normed hidden

// ---------------- helpers ----------------
__device__ __forceinline__ float block_sum(float v) {
    __shared__ float sh[8];
    int lane = threadIdx.x & 31, w = threadIdx.x >> 5;
#pragma unroll
    for (int o = 16; o; o >>= 1) v += __shfl_xor_sync(0xffffffffu, v, o);
    __syncthreads();
    if (lane == 0) sh[w] = v;
    __syncthreads();
    float r = sh[0];
#pragma unroll
    for (int i = 1; i < 8; i++) r += sh[i];
    return r;
}

#define FMA8(w4, x0, x1)                                                   \
    a[0] += (x0) * (w4).x; a[1] += (x0) * (w4).y;                          \
    a[2] += (x0) * (w4).z; a[3] += (x0) * (w4).w;                          \
    a[4] += (x1) * (w4).x; a[5] += (x1) * (w4).y;                          \
    a[6] += (x1) * (w4).z; a[7] += (x1) * (w4).w;

// A tile = 64 cols x 128 rows. Thread (rr = t>>4, c4 = t&15) loads 8 float4.
struct Tile { const float* p; const float* x0; const float* x1; };

template<int LD>
__device__ __forceinline__ void load8(float4* w, const float* p) {
#pragma unroll
    for (int r = 0; r < 8; r++)
        w[r] = *(const float4*)(p + (size_t)(r * 16) * LD);
}

__device__ __forceinline__ void fma_tile(float* a, const float4* w,
                                         const Tile& T, int rr) {
#pragma unroll
    for (int r = 0; r < 8; r++) {
        int d = rr + r * 16;
        float x0 = T.x0[d], x1 = T.x1[d];
        FMA8(w[r], x0, x1);
    }
}

// reduce a[8] over the 16 row-threads per col-quad; reusable across tiles.
__device__ __forceinline__ bool tile_reduce(float* a, float& s, int& b, int& col) {
    __shared__ float red[8][16][8];
    int t = threadIdx.x, lane = t & 31, wid = t >> 5;
    __syncthreads();                       // protect red[] from previous tile's reads
#pragma unroll
    for (int j = 0; j < 8; j++) a[j] += __shfl_xor_sync(0xffffffffu, a[j], 16);
    if (lane < 16)
#pragma unroll
        for (int j = 0; j < 8; j++) red[wid][lane][j] = a[j];
    __syncthreads();
    if (t >= 128) return false;
    int c4 = t >> 3, j = t & 7;
    float acc = 0.f;
#pragma unroll
    for (int w = 0; w < 8; w++) acc += red[w][c4][j];
    s = acc; b = j >> 2; col = c4 * 4 + (j & 3);
    return true;
}

// grid-strided, double-buffered tile streamer.
template<int LD, class TF, class OF>
__device__ __forceinline__ void gemv_stream(int ntiles, const TF& tf, const OF& of) {
    float4 wA[8], wB[8];
    int rr = threadIdx.x >> 4;
    int tauA = blockIdx.x;
    if (tauA >= ntiles) return;
    Tile A = tf(tauA);
    load8<LD>(wA, A.p);
    for (;;) {
        int tauB = tauA + GRIDSZ;
        bool hasB = tauB < ntiles;
        Tile B;
        if (hasB) { B = tf(tauB); load8<LD>(wB, B.p); }
        {
            float a[8] = {0,0,0,0,0,0,0,0};
            fma_tile(a, wA, A, rr);
            float s; int b, col;
            if (tile_reduce(a, s, b, col)) of(tauA, s, b, col);
        }
        if (!hasB) break;
        int tauC = tauB + GRIDSZ;
        bool hasC = tauC < ntiles;
        if (hasC) { A = tf(tauC); load8<LD>(wA, A.p); }
        {
            float a[8] = {0,0,0,0,0,0,0,0};
            fma_tile(a, wB, B, rr);
            float s; int b, col;
            if (tile_reduce(a, s, b, col)) of(tauB, s, b, col);
        }
        if (!hasC) break;
        tauA = tauC;
    }
}

// rms prologue: xs[b][i] = rms(g_h[b]) * gamma[i]
__device__ __forceinline__ void rms_x(const float* __restrict__ gamma,
                                      float (*xs)[DIM]) {
    int t = threadIdx.x;
    float s0 = 0.f, s1 = 0.f;
    for (int i = t; i < DIM; i += 256) {
        float v0 = g_h[0][i], v1 = g_h[1][i];
        xs[0][i] = v0; xs[1][i] = v1;
        s0 += v0 * v0; s1 += v1 * v1;
    }
    s0 = block_sum(s0);
    s1 = block_sum(s1);
    float r0 = rsqrtf(s0 * (1.f / DIM) + 1e-5f);
    float r1 = rsqrtf(s1 * (1.f / DIM) + 1e-5f);
    for (int i = t; i < DIM; i += 256) {
        float g = gamma[i];
        xs[0][i] *= r0 * g;
        xs[1][i] *= r1 * g;
    }
    __syncthreads();
}

// ---------------- init ----------------
__global__ void k_init(const float* __restrict__ emb) {
    int i = blockIdx.x * blockDim.x + threadIdx.x;
    if (i < 2 * DIM) g_h[i / DIM][i % DIM] = emb[i];
    int z = i - 2 * DIM;
    if (z >= 0) {
        if (z < 2 * 3 * DIM)            ((float*)g_qkv[0])[z] = 0.f;
        else if (z < 2*3*DIM + 4*FFN)   ((float*)g_gp[0])[z - 2*3*DIM] = 0.f;
    }
}

// ---------------- K1: rms1 + QKV. 384 tiles -------------------------------
struct QkvTF {
    const float *wq, *wk, *wv;
    const float *xs0, *xs1;
    __device__ Tile operator()(int tau) const {
        int cg = tau % 48, ks = tau / 48;
        int e0 = cg * 64;
        const float* W = wq; int ec = e0;
        if (e0 >= 2 * DIM)    { W = wv; ec = e0 - 2 * DIM; }
        else if (e0 >= DIM)   { W = wk; ec = e0 - DIM; }
        int t = threadIdx.x;
        Tile T;
        T.p  = W + (size_t)(ks * 128 + (t >> 4)) * DIM + ec + 4 * (t & 15);
        T.x0 = xs0 + ks * 128;
        T.x1 = xs1 + ks * 128;
        return T;
    }
};
struct QkvOF {
    int par;
    __device__ void operator()(int tau, float s, int b, int col) const {
        int cg = tau % 48;
        atomicAdd(&g_qkv[par][b][cg * 64 + col], s);
    }
};
__global__ void __launch_bounds__(256, 2) k_qkv(const float* __restrict__ wq,
                                                const float* __restrict__ wk,
                                                const float* __restrict__ wv,
                                                const float* __restrict__ ln1,
                                                int par) {
    __shared__ float xs[2][DIM];
    rms_x(ln1, xs);
    QkvTF tf{wq, wk, wv, xs[0], xs[1]};
    QkvOF of{par};
    gemv_stream<DIM>(384, tf, of);
}

// ---------------- K2: RoPE + attn + O GEMV. grid 256 = 16cg x 16head ------
__global__ void __launch_bounds__(256, 2) k_attn(const float* __restrict__ wo,
                                                 const int* __restrict__ cpos,
                                                 int par) {
    __shared__ float xo[2][HD];
    int t = threadIdx.x, lane = t & 31, wid = t >> 5;
    int cg = blockIdx.x & 15, ks = blockIdx.x >> 4;   // ks = head
    int rr = t >> 4, c4 = t & 15;

    if (blockIdx.x < 16) {
        float* z = (float*)g_qkv[par ^ 1] + blockIdx.x * 384;
        for (int i = t; i < 384; i += 256) z[i] = 0.f;
    }

    if (wid < 2) {
        int b = wid;
        const float* q = &g_qkv[par][b][ks * HD];
        const float* k = &g_qkv[par][b][DIM + ks * HD];
        const float* v = &g_qkv[par][b][2 * DIM + ks * HD];
        int pos = cpos[0];
        float inv_freq = __expf(-(float)(2 * lane) * (1.f / HD) * logf(10000.f));
        float ang = (float)pos * inv_freq;
        float cs = cosf(ang), sn = sinf(ang);
        float q1 = q[lane], q2 = q[lane + 32];
        float k1 = k[lane], k2 = k[lane + 32];
        float q1r = q1 * cs - q2 * sn, q2r = q2 * cs + q1 * sn;
        float k1r = k1 * cs - k2 * sn, k2r = k2 * cs + k1 * sn;
        float dot = q1r * k1r + q2r * k2r;
#pragma unroll
        for (int o = 16; o; o >>= 1) dot += __shfl_xor_sync(0xffffffffu, dot, o);
        float sc = dot * 0.125f;
        float m = fmaxf(sc, 0.f);
        float es = __expf(sc - m);
        float w = es / (es + 2047.f * __expf(-m));
        xo[b][lane]      = w * v[lane];
        xo[b][lane + 32] = w * v[lane + 32];
    }
    __syncthreads();

    int e0 = cg * 64, RB0 = ks * 64;
    const float* pthr = wo + (size_t)(RB0 + rr) * DIM + e0 + 4 * c4;
    float4 w[4];
#pragma unroll
    for (int r = 0; r < 4; r++)
        w[r] = *(const float4*)(pthr + (size_t)(r * 16) * DIM);
    float a[8] = {0,0,0,0,0,0,0,0};
#pragma unroll
    for (int r = 0; r < 4; r++) {
        int d = rr + r * 16;
        float x0 = xo[0][d], x1 = xo[1][d];
        FMA8(w[r], x0, x1);
    }
    float s; int b, col;
    if (tile_reduce(a, s, b, col))
        atomicAdd(&g_h[b][e0 + col], s);
}

// ---------------- K3: rms2 + gate|up. 704 tiles ----------------------------
struct GuTF {
    const float *wg, *wu;
    const float *xs0, *xs1;
    __device__ Tile operator()(int tau) const {
        int cg = tau % 88, ks = tau / 88;
        int half = cg >= 44;
        int e0 = (cg - half * 44) * 64;
        const float* W = half ? wu : wg;
        int t = threadIdx.x;
        Tile T;
        T.p  = W + (size_t)(ks * 128 + (t >> 4)) * FFN + e0 + 4 * (t & 15);
        T.x0 = xs0 + ks * 128;
        T.x1 = xs1 + ks * 128;
        return T;
    }
};
struct GuOF {
    int par;
    __device__ void operator()(int tau, float s, int b, int col) const {
        int cg = tau % 88;
        int half = cg >= 44;
        int e0 = (cg - half * 44) * 64;
        atomicAdd(&g_gp[par][half][b][e0 + col], s);
    }
};
__global__ void __launch_bounds__(256, 2) k_gateup(const float* __restrict__ wg,
                                                   const float* __restrict__ wu,
                                                   const float* __restrict__ ln2,
                                                   int par) {
    __shared__ float xs[2][DIM];
    rms_x(ln2, xs);
    GuTF tf{wg, wu, xs[0], xs[1]};
    GuOF of{par};
    gemv_stream<FFN>(704, tf, of);
}

// ---------------- K4: silu + down. 352 tiles -------------------------------
struct DnTF {
    const float* wd;
    const float *xs0, *xs1;
    __device__ Tile operator()(int tau) const {
        int cg = tau & 15, ks = tau >> 4;
        int t = threadIdx.x;
        Tile T;
        T.p  = wd + (size_t)(ks * 128 + (t >> 4)) * DIM + cg * 64 + 4 * (t & 15);
        T.x0 = xs0 + ks * 128;
        T.x1 = xs1 + ks * 128;
        return T;
    }
};
struct DnOF {
    __device__ void operator()(int tau, float s, int b, int col) const {
        int cg = tau & 15;
        atomicAdd(&g_h[b][cg * 64 + col], s);
    }
};
__global__ void __launch_bounds__(256, 2) k_down(const float* __restrict__ wd,
                                                 int par) {
    __shared__ float xs[2][FFN];
    int t = threadIdx.x;

    if (blockIdx.x < 11) {
        float* z = (float*)g_gp[par ^ 1] + blockIdx.x * 1024;
        for (int i = t; i < 1024; i += 256) z[i] = 0.f;
    }

    for (int i = t; i < FFN; i += 256) {
        float g0 = g_gp[par][0][0][i], u0 = g_gp[par][1][0][i];
        float g1 = g_gp[par][0][1][i], u1 = g_gp[par][1][1][i];
        xs[0][i] = g0 / (1.f + __expf(-g0)) * u0;
        xs[1][i] = g1 / (1.f + __expf(-g1)) * u1;
    }
    __syncthreads();

    DnTF tf{wd, xs[0], xs[1]};
    DnOF of{};
    gemv_stream<DIM>(352, tf, of);
}

// ---------------- K5: final rms + zero logits. grid 17 ---------------------
__global__ void __launch_bounds__(256) k_final(const float* __restrict__ normw,
                                               float* __restrict__ out) {
    if (blockIdx.x < 16) {
        int base = 2 * DIM + blockIdx.x * 4000;
        for (int i = threadIdx.x; i < 4000; i += 256)
            out[base + i] = 0.f;
        return;
    }
    __shared__ float xs[2][DIM];
    rms_x(normw, xs);
    int t = threadIdx.x;
    for (int i = t; i < DIM; i += 256) {
        g_hn[0][i] = xs[0][i];
        g_hn[1][i] = xs[1][i];
        out[i]       = xs[0][i];
        out[DIM + i] = xs[1][i];
    }
}

// ---------------- K6: lm_head. 4000 tiles ----------------------------------
struct LmTF {
    const float* wlm;
    const float *xs0, *xs1;
    __device__ Tile operator()(int tau) const {
        int cg = tau % 500, ks = tau / 500;
        int t = threadIdx.x;
        Tile T;
        T.p  = wlm + (size_t)(ks * 128 + (t >> 4)) * VOCAB + cg * 64 + 4 * (t & 15);
        T.x0 = xs0 + ks * 128;
        T.x1 = xs1 + ks * 128;
        return T;
    }
};
struct LmOF {
    float* out;
    __device__ void operator()(int tau, float s, int b, int col) const {
        int cg = tau % 500;
        atomicAdd(&out[2 * DIM + (size_t)b * VOCAB + cg * 64 + col], s);
    }
};
__global__ void __launch_bounds__(256, 2) k_lmhead(const float* __restrict__ wlm,
                                                   float* __restrict__ out) {
    __shared__ float xs[2][DIM];
    int t = threadIdx.x;
    for (int i = t; i < DIM; i += 256) {
        xs[0][i] = g_hn[0][i];
        xs[1][i] = g_hn[1][i];
    }
    __syncthreads();
    LmTF tf{wlm, xs[0], xs[1]};
    LmOF of{out};
    gemv_stream<VOCAB>(4000, tf, of);
}

// ---------------- launcher ----------------
extern "C" void kernel_launch(void* const* d_in, const int* in_sizes, int n_in,
                              void* d_out, int out_size) {
    const float* emb  = (const float*)d_in[0];
    const int*   cpos = (const int*)d_in[2];
    const float* wq   = (const float*)d_in[4];
    const float* wk   = (const float*)d_in[5];
    const float* wv   = (const float*)d_in[6];
    const float* wo   = (const float*)d_in[7];
    const float* wg   = (const float*)d_in[8];
    const float* wu   = (const float*)d_in[9];
    const float* wd   = (const float*)d_in[10];
    const float* ln1  = (const float*)d_in[11];
    const float* ln2  = (const float*)d_in[12];
    const float* nw   = (const float*)d_in[13];
    const float* wlm  = (const float*)d_in[14];
    float* out = (float*)d_out;

    k_init<<<19, 1024>>>(emb);
    for (int l = 0; l < NL; l++) {
        int par = l & 1;
        size_t oqk = (size_t)l * DIM * DIM;
        size_t ogu = (size_t)l * DIM * FFN;
        k_qkv   <<<GRIDSZ, 256>>>(wq + oqk, wk + oqk, wv + oqk, ln1 + l * DIM, par);
        k_attn  <<<256,    256>>>(wo + oqk, cpos, par);
        k_gateup<<<GRIDSZ, 256>>>(wg + ogu, wu + ogu, ln2 + l * DIM, par);
        k_down  <<<GRIDSZ, 256>>>(wd + ogu, par);
    }
    k_final <<<17,     256>>>(nw, out);
    k_lmhead<<<GRIDSZ, 256>>>(wlm, out);
}